// round 3
// baseline (speedup 1.0000x reference)
#include <cuda_runtime.h>
#include <cstdint>
#include <math.h>

#define NB 32
#define NS 512
#define NI 128
#define NH 128
#define NO 32
#define NG 384   // 3*H

// Scratch (device globals; no allocation allowed in kernel_launch)
__device__ float g_ih[(size_t)NB * NS * NG];          // [b][s][g]   25 MB
__device__ float g_coef[(size_t)NS * NB * 4 * NH];    // [s][b][plane][j] 33.5 MB

// ---------------- helpers ----------------

__device__ __forceinline__ float sigf(float x) { return 1.0f / (1.0f + expf(-x)); }

__device__ __forceinline__ unsigned long long pack2(float lo, float hi) {
    unsigned long long r;
    asm("mov.b64 %0, {%1,%2};" : "=l"(r)
        : "r"(__float_as_uint(lo)), "r"(__float_as_uint(hi)));
    return r;
}
__device__ __forceinline__ void unpack2(unsigned long long v, float& lo, float& hi) {
    unsigned a, b;
    asm("mov.b64 {%0,%1}, %2;" : "=r"(a), "=r"(b) : "l"(v));
    lo = __uint_as_float(a); hi = __uint_as_float(b);
}
// packed fp32x2 FMA (FFMA2) — 2x fp32 FMA throughput on sm_103a
__device__ __forceinline__ void ffma2(unsigned long long& acc,
                                      unsigned long long a, unsigned long long b) {
    asm("fma.rn.f32x2 %0, %1, %2, %0;" : "+l"(acc) : "l"(a), "l"(b));
}

// ---------------- Phase A: ih = x @ W_ih^T + b_ih ----------------
// M=16384 (b*512+s), N=384, K=128. CTA tile 64(M) x 128(N), 256 threads,
// K in 4 chunks of 32 (keeps static smem at 24 KB). f32x2-packed FMAs.
__global__ void __launch_bounds__(256) ih_gemm_kernel(
    const float* __restrict__ x, const float* __restrict__ W_ih,
    const float* __restrict__ b_ih)
{
    __shared__ __align__(16) float As[64 * 32];    // [m][k]
    __shared__ __align__(16) float Bs[32 * 128];   // [k][n] (transposed W tile)
    const int m0 = blockIdx.x * 64;
    const int n0 = blockIdx.y * 128;
    const int tid = threadIdx.x;
    const int tx = tid & 15;    // n-group: covers n = tx*8 .. tx*8+7
    const int ty = tid >> 4;    // m-group: rows ty*4 .. ty*4+3

    unsigned long long acc[4][4];
#pragma unroll
    for (int a = 0; a < 4; a++)
#pragma unroll
        for (int c = 0; c < 4; c++) acc[a][c] = 0ull;

    const float4* x4 = (const float4*)x;
    const float4* w4 = (const float4*)W_ih;

    for (int kc = 0; kc < 4; kc++) {
        const int k0q = kc * 8;  // k offset in float4 units
        __syncthreads();
        // Load A chunk: 64x32 floats = 512 float4
#pragma unroll
        for (int r = 0; r < 2; r++) {
            int idx = tid + r * 256;
            int m = idx >> 3, kq = idx & 7;
            ((float4*)As)[idx] = x4[(size_t)(m0 + m) * 32 + k0q + kq];
        }
        // Load B chunk transposed: 128x32 floats = 1024 float4
#pragma unroll
        for (int r = 0; r < 4; r++) {
            int idx = tid + r * 256;
            int n = idx >> 3, kq = idx & 7;
            float4 v = w4[(size_t)(n0 + n) * 32 + k0q + kq];
            Bs[(kq * 4 + 0) * 128 + n] = v.x;
            Bs[(kq * 4 + 1) * 128 + n] = v.y;
            Bs[(kq * 4 + 2) * 128 + n] = v.z;
            Bs[(kq * 4 + 3) * 128 + n] = v.w;
        }
        __syncthreads();
#pragma unroll 8
        for (int k = 0; k < 32; k++) {
            unsigned long long a2[4];
#pragma unroll
            for (int mm = 0; mm < 4; mm++) {
                float av = As[(ty * 4 + mm) * 32 + k];
                a2[mm] = pack2(av, av);
            }
            const ulonglong2* bp = (const ulonglong2*)(Bs + k * 128 + tx * 8);
            ulonglong2 p0 = bp[0], p1 = bp[1];
            unsigned long long b2[4] = {p0.x, p0.y, p1.x, p1.y};
#pragma unroll
            for (int mm = 0; mm < 4; mm++)
#pragma unroll
                for (int c = 0; c < 4; c++)
                    ffma2(acc[mm][c], a2[mm], b2[c]);
        }
    }
    // Epilogue: add bias, store 8 contiguous floats per (thread, m-row) as 2 float4
#pragma unroll
    for (int mm = 0; mm < 4; mm++) {
        int m = m0 + ty * 4 + mm;
        float* orow = g_ih + (size_t)m * NG + n0 + tx * 8;
        float vals[8];
#pragma unroll
        for (int c = 0; c < 4; c++) {
            float lo, hi;
            unpack2(acc[mm][c], lo, hi);
            int n = n0 + tx * 8 + c * 2;
            vals[c * 2]     = lo + b_ih[n];
            vals[c * 2 + 1] = hi + b_ih[n + 1];
        }
        ((float4*)orow)[0] = make_float4(vals[0], vals[1], vals[2], vals[3]);
        ((float4*)orow)[1] = make_float4(vals[4], vals[5], vals[6], vals[7]);
    }
}

// ---------------- Phase B: sequential GRU scan ----------------
// One CTA per batch element b (32 CTAs). 384 threads; thread g holds the full
// 128-float row of W_hh in registers (as 64 packed f32x2), does the 384x128
// matvec per step with FFMA2, h broadcast from smem. Threads g<128 compute
// gates + Jacobian coefficients and write them to g_coef.
__global__ void __launch_bounds__(384, 1) gru_scan_kernel(
    const float* __restrict__ W_hh, const float* __restrict__ b_hh,
    const float* __restrict__ W_y,  const float* __restrict__ b_y,
    float* __restrict__ out)
{
    const int b = blockIdx.x;
    const int g = threadIdx.x;   // 0..383

    __shared__ __align__(16) float h_sh[NH];
    __shared__ float hh_sh[NG];

    // Register-resident weight row: 64 x u64 = 128 regs
    unsigned long long w2[64];
    const unsigned long long* wrow =
        (const unsigned long long*)(W_hh + (size_t)g * NH);
#pragma unroll
    for (int k2 = 0; k2 < 64; k2++) w2[k2] = wrow[k2];
    const float bh = b_hh[g];

    if (g < NH) h_sh[g] = 0.0f;
    __syncthreads();

    const float* ihp = g_ih + (size_t)b * NS * NG;

    for (int s = 0; s < NS; s++) {
        // Prefetch this step's ih values + h_prev (epilogue threads only)
        float ihr = 0.f, ihz = 0.f, ihn = 0.f, hp = 0.f;
        if (g < NH) {
            const float* ihs = ihp + (size_t)s * NG;
            ihr = ihs[g];
            ihz = ihs[NH + g];
            ihn = ihs[2 * NH + g];
            hp  = h_sh[g];
        }
        // hh[g] = W_hh[g,:] . h  (packed f32x2, 4 accumulators for ILP)
        unsigned long long acc[4] = {0ull, 0ull, 0ull, 0ull};
        const ulonglong2* h4 = (const ulonglong2*)h_sh;
#pragma unroll
        for (int k4 = 0; k4 < 32; k4++) {
            ulonglong2 hv = h4[k4];
            ffma2(acc[(2 * k4) & 3],     w2[2 * k4],     hv.x);
            ffma2(acc[(2 * k4 + 1) & 3], w2[2 * k4 + 1], hv.y);
        }
        float l0, h0, l1, h1, l2, h2, l3, h3;
        unpack2(acc[0], l0, h0); unpack2(acc[1], l1, h1);
        unpack2(acc[2], l2, h2); unpack2(acc[3], l3, h3);
        float sum = ((l0 + h0) + (l1 + h1)) + ((l2 + h2) + (l3 + h3)) + bh;
        hh_sh[g] = sum;
        __syncthreads();

        if (g < NH) {
            float hr = sum;                 // this thread computed the r-row
            float hz = hh_sh[NH + g];
            float M  = hh_sh[2 * NH + g];
            float r = sigf(ihr + hr);
            float z = sigf(ihz + hz);
            float n = tanhf(ihn + r * M);
            float hnew = (1.0f - z) * n + z * hp;
            float c67 = (1.0f - n * n) * (1.0f - z);
            float cr = r * (1.0f - r) * M * c67;
            float cn = r * c67;
            float cz = z * (1.0f - z) * (hp - n);
            size_t cb = ((size_t)(s * NB + b)) * (4 * NH);
            g_coef[cb + g]           = cr;
            g_coef[cb + NH + g]      = cn;
            g_coef[cb + 2 * NH + g]  = cz;
            g_coef[cb + 3 * NH + g]  = z;
            h_sh[g] = hnew;
        }
        __syncthreads();
    }

    // y = h_last @ W_y^T + b_y
    if (g < NO) {
        float acc = b_y[g];
        const float* wy = W_y + (size_t)g * NH;
#pragma unroll
        for (int j = 0; j < NH; j++) acc = fmaf(wy[j], h_sh[j], acc);
        out[b * NO + g] = acc;
    }
}

// ---------------- Phase C: materialize the Jacobian (HBM-write-bound) ----------------
// jcbT_out[511-s, b, i, j] = Whh[j,i]*cr + Whh[2H+j,i]*cn + Whh[H+j,i]*cz + (i==j)*z
// Thread owns (i, j0..j0+3); its 12 W values live in registers across ALL tiles.
__global__ void __launch_bounds__(512) jac_kernel(
    const float* __restrict__ W_hh, float* __restrict__ out)
{
    const int tid = threadIdx.x;
    const int j4 = tid & 31;        // j block: j0 = j4*4
    const int iloc = tid >> 5;      // 0..15
    const int i = blockIdx.y * 16 + iloc;
    const int j0 = j4 * 4;

    float wr[4], wz[4], wn[4];
#pragma unroll
    for (int d = 0; d < 4; d++) {
        int j = j0 + d;
        wr[d] = W_hh[(size_t)j * NH + i];
        wz[d] = W_hh[(size_t)(NH + j) * NH + i];
        wn[d] = W_hh[(size_t)(2 * NH + j) * NH + i];
    }

    float* jac = out + NB * NO;     // y occupies the first 1024 floats

    for (int t = blockIdx.x; t < NS * NB; t += gridDim.x) {
        int s = t >> 5;
        int b = t & 31;
        const float4* cp = (const float4*)(g_coef + (size_t)t * (4 * NH));
        float4 cr = cp[j4];
        float4 cn = cp[32 + j4];
        float4 cz = cp[64 + j4];
        float4 zz = cp[96 + j4];
        float4 v;
        v.x = fmaf(wr[0], cr.x, fmaf(wn[0], cn.x, wz[0] * cz.x));
        v.y = fmaf(wr[1], cr.y, fmaf(wn[1], cn.y, wz[1] * cz.y));
        v.z = fmaf(wr[2], cr.z, fmaf(wn[2], cn.z, wz[2] * cz.z));
        v.w = fmaf(wr[3], cr.w, fmaf(wn[3], cn.w, wz[3] * cz.w));
        if (i == j0)     v.x += zz.x;
        if (i == j0 + 1) v.y += zz.y;
        if (i == j0 + 2) v.z += zz.z;
        if (i == j0 + 3) v.w += zz.w;
        size_t off = ((size_t)((NS - 1 - s) * NB + b)) * (size_t)(NH * NH)
                   + (size_t)i * NH + j0;
        *(float4*)(jac + off) = v;
    }
}

// ---------------- launch ----------------
extern "C" void kernel_launch(void* const* d_in, const int* in_sizes, int n_in,
                              void* d_out, int out_size) {
    const float* x    = (const float*)d_in[0];
    const float* W_ih = (const float*)d_in[1];
    const float* W_hh = (const float*)d_in[2];
    const float* b_ih = (const float*)d_in[3];
    const float* b_hh = (const float*)d_in[4];
    const float* W_y  = (const float*)d_in[5];
    const float* b_y  = (const float*)d_in[6];
    float* out = (float*)d_out;

    ih_gemm_kernel<<<dim3(256, 3), 256>>>(x, W_ih, b_ih);
    gru_scan_kernel<<<NB, NG>>>(W_hh, b_hh, W_y, b_y, out);
    jac_kernel<<<dim3(256, 8), 512>>>(W_hh, out);
}

// round 4
// speedup vs baseline: 1.4226x; 1.4226x over previous
#include <cuda_runtime.h>
#include <cstdint>
#include <math.h>

#define NB 32
#define NS 512
#define NI 128
#define NH 128
#define NO 32
#define NG 384   // 3*H
#define NCONS 116           // consumer CTAs in mega kernel (148-32)
#define FLAG_STEP 8         // steps per readiness flag
#define NFLAG (NS / FLAG_STEP)

// Scratch (device globals; no allocation allowed in kernel_launch)
__device__ float g_ih[(size_t)NB * NS * NG];          // [b][s][g]
__device__ float g_coef[(size_t)NS * NB * 4 * NH];    // [s*32+b][plane][j]
__device__ float g_wT[(size_t)NH * NG];               // [i][plane*128+j] = W_hh[plane*128+j][i]
__device__ unsigned g_flag[NFLAG];                    // per-8-step completion counters (0..32)

// ---------------- helpers ----------------
__device__ __forceinline__ float ex2f(float x) {
    float r; asm("ex2.approx.f32 %0, %1;" : "=f"(r) : "f"(x)); return r;
}
__device__ __forceinline__ float rcpf(float x) {
    float r; asm("rcp.approx.f32 %0, %1;" : "=f"(r) : "f"(x)); return r;
}
__device__ __forceinline__ float sigf(float x) {
    return rcpf(1.0f + ex2f(-1.4426950408889634f * x));
}
__device__ __forceinline__ float tanh_fast(float x) {
    float e = ex2f(2.8853900817779268f * x);   // exp2(2x*log2e) = e^{2x}
    return 1.0f - 2.0f * rcpf(e + 1.0f);
}
__device__ __forceinline__ unsigned long long pack2(float lo, float hi) {
    unsigned long long r;
    asm("mov.b64 %0, {%1,%2};" : "=l"(r)
        : "r"(__float_as_uint(lo)), "r"(__float_as_uint(hi)));
    return r;
}
__device__ __forceinline__ void unpack2(unsigned long long v, float& lo, float& hi) {
    unsigned a, b;
    asm("mov.b64 {%0,%1}, %2;" : "=r"(a), "=r"(b) : "l"(v));
    lo = __uint_as_float(a); hi = __uint_as_float(b);
}
__device__ __forceinline__ void ffma2(unsigned long long& acc,
                                      unsigned long long a, unsigned long long b) {
    asm("fma.rn.f32x2 %0, %1, %2, %0;" : "+l"(acc) : "l"(a), "l"(b));
}
__device__ __forceinline__ unsigned ld_acquire(const unsigned* p) {
    unsigned v;
    asm volatile("ld.acquire.gpu.global.b32 %0, [%1];" : "=r"(v) : "l"(p));
    return v;
}
__device__ __forceinline__ void red_add(unsigned* p, unsigned v) {
    asm volatile("red.relaxed.gpu.global.add.u32 [%0], %1;" :: "l"(p), "r"(v));
}

// ---------------- Phase A: ih = x @ W_ih^T + b_ih (+ side jobs) ----------------
// M=16384, N=384, K=128. CTA tile 64x128, 256 thr, K in 4 chunks of 32,
// register double-buffered global loads. Side jobs: zero flags, transpose W_hh.
__global__ void __launch_bounds__(256) ih_gemm_kernel(
    const float* __restrict__ x, const float* __restrict__ W_ih,
    const float* __restrict__ b_ih, const float* __restrict__ W_hh)
{
    __shared__ __align__(16) float As[64 * 32];
    __shared__ __align__(16) float Bs[32 * 128];
    const int m0 = blockIdx.x * 64;
    const int n0 = blockIdx.y * 128;
    const int tid = threadIdx.x;
    const int tx = tid & 15;
    const int ty = tid >> 4;

    // side job 1: zero flags
    if (blockIdx.x == 0 && blockIdx.y == 0 && tid < NFLAG) g_flag[tid] = 0u;
    // side job 2: transpose W_hh -> g_wT  (192 blocks of y==2 cover 49152 elems)
    if (blockIdx.y == 2 && blockIdx.x < 192) {
        int o = blockIdx.x * 256 + tid;       // o = i*384 + c
        int i = o / NG, c = o - i * NG;
        g_wT[o] = W_hh[(size_t)c * NH + i];
    }

    unsigned long long acc[4][4];
#pragma unroll
    for (int a = 0; a < 4; a++)
#pragma unroll
        for (int c = 0; c < 4; c++) acc[a][c] = 0ull;

    const float4* x4 = (const float4*)x;
    const float4* w4 = (const float4*)W_ih;
    const int lm = tid >> 3;     // 0..31
    const int lk = tid & 7;      // 0..7

    float4 ra[2], rb[4];
#define LOAD_CHUNK(kc)                                                          \
    {                                                                           \
        _Pragma("unroll")                                                       \
        for (int r = 0; r < 2; r++)                                             \
            ra[r] = x4[(size_t)(m0 + lm + r * 32) * 32 + (kc) * 8 + lk];        \
        _Pragma("unroll")                                                       \
        for (int r = 0; r < 4; r++)                                             \
            rb[r] = w4[(size_t)(n0 + lm + r * 32) * 32 + (kc) * 8 + lk];        \
    }

    LOAD_CHUNK(0);
#pragma unroll
    for (int kc = 0; kc < 4; kc++) {
        __syncthreads();
        // store regs -> smem
#pragma unroll
        for (int r = 0; r < 2; r++)
            ((float4*)As)[tid + r * 256] = ra[r];
#pragma unroll
        for (int r = 0; r < 4; r++) {
            int n = lm + r * 32;
            Bs[(lk * 4 + 0) * 128 + n] = rb[r].x;
            Bs[(lk * 4 + 1) * 128 + n] = rb[r].y;
            Bs[(lk * 4 + 2) * 128 + n] = rb[r].z;
            Bs[(lk * 4 + 3) * 128 + n] = rb[r].w;
        }
        __syncthreads();
        if (kc < 3) LOAD_CHUNK(kc + 1);
#pragma unroll 8
        for (int k = 0; k < 32; k++) {
            unsigned long long a2[4];
#pragma unroll
            for (int mm = 0; mm < 4; mm++) {
                float av = As[(ty * 4 + mm) * 32 + k];
                a2[mm] = pack2(av, av);
            }
            const ulonglong2* bp = (const ulonglong2*)(Bs + k * 128 + tx * 8);
            ulonglong2 p0 = bp[0], p1 = bp[1];
            unsigned long long b2[4] = {p0.x, p0.y, p1.x, p1.y};
#pragma unroll
            for (int mm = 0; mm < 4; mm++)
#pragma unroll
                for (int c = 0; c < 4; c++)
                    ffma2(acc[mm][c], a2[mm], b2[c]);
        }
    }
#undef LOAD_CHUNK
    // Epilogue: bias + store
#pragma unroll
    for (int mm = 0; mm < 4; mm++) {
        int m = m0 + ty * 4 + mm;
        float* orow = g_ih + (size_t)m * NG + n0 + tx * 8;
        float vals[8];
#pragma unroll
        for (int c = 0; c < 4; c++) {
            float lo, hi;
            unpack2(acc[mm][c], lo, hi);
            int n = n0 + tx * 8 + c * 2;
            vals[c * 2]     = lo + b_ih[n];
            vals[c * 2 + 1] = hi + b_ih[n + 1];
        }
        ((float4*)orow)[0] = make_float4(vals[0], vals[1], vals[2], vals[3]);
        ((float4*)orow)[1] = make_float4(vals[4], vals[5], vals[6], vals[7]);
    }
}

// ---------------- Mega kernel: scan producers (CTA 0..31) + jac consumers ----------------
__global__ void __launch_bounds__(384, 1) mega_kernel(
    const float* __restrict__ W_hh, const float* __restrict__ b_hh,
    const float* __restrict__ W_y,  const float* __restrict__ b_y,
    float* __restrict__ out)
{
    const int tid = threadIdx.x;

    if (blockIdx.x < NB) {
        // ================= PRODUCER: GRU scan for batch b =================
        const int b = blockIdx.x;
        const int g = tid;

        __shared__ __align__(16) float h_sh[NH];
        __shared__ float hh_sh[NG];

        unsigned long long w2[64];
        const unsigned long long* wrow =
            (const unsigned long long*)(W_hh + (size_t)g * NH);
#pragma unroll
        for (int k2 = 0; k2 < 64; k2++) w2[k2] = wrow[k2];
        const float bh = b_hh[g];

        if (g < NH) h_sh[g] = 0.0f;
        __syncthreads();

        const float* ihp = g_ih + (size_t)b * NS * NG;

        for (int s = 0; s < NS; s++) {
            float ihr = 0.f, ihz = 0.f, ihn = 0.f, hp = 0.f;
            if (g < NH) {
                const float* ihs = ihp + (size_t)s * NG;
                ihr = ihs[g];
                ihz = ihs[NH + g];
                ihn = ihs[2 * NH + g];
                hp  = h_sh[g];
            }
            unsigned long long acc[4] = {0ull, 0ull, 0ull, 0ull};
            const ulonglong2* h4 = (const ulonglong2*)h_sh;
#pragma unroll
            for (int k4 = 0; k4 < 32; k4++) {
                ulonglong2 hv = h4[k4];
                ffma2(acc[(2 * k4) & 3],     w2[2 * k4],     hv.x);
                ffma2(acc[(2 * k4 + 1) & 3], w2[2 * k4 + 1], hv.y);
            }
            float l0, h0, l1, h1, l2, h2, l3, h3;
            unpack2(acc[0], l0, h0); unpack2(acc[1], l1, h1);
            unpack2(acc[2], l2, h2); unpack2(acc[3], l3, h3);
            float sum = ((l0 + h0) + (l1 + h1)) + ((l2 + h2) + (l3 + h3)) + bh;
            hh_sh[g] = sum;
            __syncthreads();

            if (g < NH) {
                float hr = sum;
                float hz = hh_sh[NH + g];
                float M  = hh_sh[2 * NH + g];
                float r = sigf(ihr + hr);
                float z = sigf(ihz + hz);
                float n = tanh_fast(ihn + r * M);
                float hnew = (1.0f - z) * n + z * hp;
                float c67 = (1.0f - n * n) * (1.0f - z);
                float cr = r * (1.0f - r) * M * c67;
                float cn = r * c67;
                float cz = z * (1.0f - z) * (hp - n);
                size_t cb = ((size_t)(s * NB + b)) * (4 * NH);
                g_coef[cb + g]          = cr;
                g_coef[cb + NH + g]     = cn;
                g_coef[cb + 2 * NH + g] = cz;
                g_coef[cb + 3 * NH + g] = z;
                h_sh[g] = hnew;
                if ((s & (FLAG_STEP - 1)) == FLAG_STEP - 1)
                    __threadfence();      // release: drain this thread's coef stores
            }
            __syncthreads();
            if (g == 0 && (s & (FLAG_STEP - 1)) == FLAG_STEP - 1)
                red_add(&g_flag[s >> 3], 1u);  // signal: 8 steps of b complete
        }

        // y = h_last @ W_y^T + b_y
        if (g < NO) {
            float a = b_y[g];
            const float* wy = W_y + (size_t)g * NH;
#pragma unroll
            for (int j = 0; j < NH; j++) a = fmaf(wy[j], h_sh[j], a);
            out[b * NO + g] = a;
        }
    } else {
        // ================= CONSUMER: Jacobian materialization =================
        const int c0 = blockIdx.x - NB;     // 0..115
        const int w = tid >> 5;             // warp 0..11 -> i rows
        const int lane = tid & 31;
        const int j0 = lane * 4;
        float* jac = out + NB * NO;

        int scready = -1;
        for (int t = c0; t < NS * NB; t += NCONS) {
            int s = t >> 5;
            int b = t & 31;
            int sc = s >> 3;
            if (sc != scready) {
                if (tid == 0) {
                    while (ld_acquire(&g_flag[sc]) < (unsigned)NB) __nanosleep(128);
                }
                __syncthreads();
                scready = sc;
            }
            const float4* cp = (const float4*)(g_coef + (size_t)t * (4 * NH));
            float4 cr = cp[lane];
            float4 cn = cp[32 + lane];
            float4 cz = cp[64 + lane];
            float4 zz = cp[96 + lane];
            float* obase = jac + ((size_t)((NS - 1 - s) * NB + b)) * (NH * NH);
            for (int i = w; i < NH; i += 12) {
                const float4* wp = (const float4*)(g_wT + (size_t)i * NG);
                float4 wr = wp[lane];          // W_hh[j, i]       (r rows)
                float4 wz = wp[32 + lane];     // W_hh[H+j, i]     (z rows)
                float4 wn = wp[64 + lane];     // W_hh[2H+j, i]    (n rows)
                float4 v;
                v.x = fmaf(wr.x, cr.x, fmaf(wn.x, cn.x, wz.x * cz.x));
                v.y = fmaf(wr.y, cr.y, fmaf(wn.y, cn.y, wz.y * cz.y));
                v.z = fmaf(wr.z, cr.z, fmaf(wn.z, cn.z, wz.z * cz.z));
                v.w = fmaf(wr.w, cr.w, fmaf(wn.w, cn.w, wz.w * cz.w));
                if ((i >> 2) == lane) {        // diagonal: j == i
                    int d = i & 3;
                    if (d == 0) v.x += zz.x;
                    else if (d == 1) v.y += zz.y;
                    else if (d == 2) v.z += zz.z;
                    else v.w += zz.w;
                }
                *(float4*)(obase + i * NH + j0) = v;
            }
        }
    }
}

// ---------------- launch ----------------
extern "C" void kernel_launch(void* const* d_in, const int* in_sizes, int n_in,
                              void* d_out, int out_size) {
    const float* x    = (const float*)d_in[0];
    const float* W_ih = (const float*)d_in[1];
    const float* W_hh = (const float*)d_in[2];
    const float* b_ih = (const float*)d_in[3];
    const float* b_hh = (const float*)d_in[4];
    const float* W_y  = (const float*)d_in[5];
    const float* b_y  = (const float*)d_in[6];
    float* out = (float*)d_out;

    ih_gemm_kernel<<<dim3(256, 3), 256>>>(x, W_ih, b_ih, W_hh);
    mega_kernel<<<NB + NCONS, NG>>>(W_hh, b_hh, W_y, b_y, out);
}

// round 5
// speedup vs baseline: 1.6754x; 1.1777x over previous
#include <cuda_runtime.h>
#include <cstdint>
#include <math.h>

#define NB 32
#define NS 512
#define NI 128
#define NH 128
#define NO 32
#define NG 384   // 3*H
#define NCONS 116           // consumer CTAs in mega kernel (148-32)
#define FLAG_STEP 8         // steps per readiness flag
#define NFLAG (NS / FLAG_STEP)

// Scratch (device globals; no allocation allowed in kernel_launch)
__device__ float g_ih[(size_t)NB * NS * NG];          // [b][s][g]
__device__ float g_coef[(size_t)NS * NB * 4 * NH];    // [s*32+b][plane][j]
__device__ float g_wT[(size_t)NH * NG];               // [i][plane*128+j] = W_hh[plane*128+j][i]
__device__ unsigned g_flag[NFLAG];                    // per-8-step completion counters (0..32)

// ---------------- helpers ----------------
__device__ __forceinline__ float ex2f(float x) {
    float r; asm("ex2.approx.f32 %0, %1;" : "=f"(r) : "f"(x)); return r;
}
__device__ __forceinline__ float rcpf(float x) {
    float r; asm("rcp.approx.f32 %0, %1;" : "=f"(r) : "f"(x)); return r;
}
__device__ __forceinline__ float sigf(float x) {
    return rcpf(1.0f + ex2f(-1.4426950408889634f * x));
}
__device__ __forceinline__ float tanh_fast(float x) {
    float e = ex2f(2.8853900817779268f * x);   // e^{2x}
    return 1.0f - 2.0f * rcpf(e + 1.0f);
}
__device__ __forceinline__ unsigned long long pack2(float lo, float hi) {
    unsigned long long r;
    asm("mov.b64 %0, {%1,%2};" : "=l"(r)
        : "r"(__float_as_uint(lo)), "r"(__float_as_uint(hi)));
    return r;
}
__device__ __forceinline__ void unpack2(unsigned long long v, float& lo, float& hi) {
    unsigned a, b;
    asm("mov.b64 {%0,%1}, %2;" : "=r"(a), "=r"(b) : "l"(v));
    lo = __uint_as_float(a); hi = __uint_as_float(b);
}
__device__ __forceinline__ void ffma2(unsigned long long& acc,
                                      unsigned long long a, unsigned long long b) {
    asm("fma.rn.f32x2 %0, %1, %2, %0;" : "+l"(acc) : "l"(a), "l"(b));
}
__device__ __forceinline__ unsigned ld_acquire(const unsigned* p) {
    unsigned v;
    asm volatile("ld.acquire.gpu.global.b32 %0, [%1];" : "=r"(v) : "l"(p));
    return v;
}
__device__ __forceinline__ void red_add_release(unsigned* p, unsigned v) {
    asm volatile("red.release.gpu.global.add.u32 [%0], %1;" :: "l"(p), "r"(v));
}

// ---------------- Phase A: ih = x @ W_ih^T + b_ih (+ side jobs) ----------------
__global__ void __launch_bounds__(256) ih_gemm_kernel(
    const float* __restrict__ x, const float* __restrict__ W_ih,
    const float* __restrict__ b_ih, const float* __restrict__ W_hh)
{
    __shared__ __align__(16) float As[64 * 32];
    __shared__ __align__(16) float Bs[32 * 128];
    const int m0 = blockIdx.x * 64;
    const int n0 = blockIdx.y * 128;
    const int tid = threadIdx.x;
    const int tx = tid & 15;
    const int ty = tid >> 4;

    // side job 1: zero flags
    if (blockIdx.x == 0 && blockIdx.y == 0 && tid < NFLAG) g_flag[tid] = 0u;
    // side job 2: transpose W_hh -> g_wT
    if (blockIdx.y == 2 && blockIdx.x < 192) {
        int o = blockIdx.x * 256 + tid;       // o = i*384 + c
        int i = o / NG, c = o - i * NG;
        g_wT[o] = W_hh[(size_t)c * NH + i];
    }

    unsigned long long acc[4][4];
#pragma unroll
    for (int a = 0; a < 4; a++)
#pragma unroll
        for (int c = 0; c < 4; c++) acc[a][c] = 0ull;

    const float4* x4 = (const float4*)x;
    const float4* w4 = (const float4*)W_ih;
    const int lm = tid >> 3;     // 0..31
    const int lk = tid & 7;      // 0..7

    float4 ra[2], rb[4];
#define LOAD_CHUNK(kc)                                                          \
    {                                                                           \
        _Pragma("unroll")                                                       \
        for (int r = 0; r < 2; r++)                                             \
            ra[r] = x4[(size_t)(m0 + lm + r * 32) * 32 + (kc) * 8 + lk];        \
        _Pragma("unroll")                                                       \
        for (int r = 0; r < 4; r++)                                             \
            rb[r] = w4[(size_t)(n0 + lm + r * 32) * 32 + (kc) * 8 + lk];        \
    }

    LOAD_CHUNK(0);
#pragma unroll
    for (int kc = 0; kc < 4; kc++) {
        __syncthreads();
#pragma unroll
        for (int r = 0; r < 2; r++)
            ((float4*)As)[tid + r * 256] = ra[r];
#pragma unroll
        for (int r = 0; r < 4; r++) {
            int n = lm + r * 32;
            Bs[(lk * 4 + 0) * 128 + n] = rb[r].x;
            Bs[(lk * 4 + 1) * 128 + n] = rb[r].y;
            Bs[(lk * 4 + 2) * 128 + n] = rb[r].z;
            Bs[(lk * 4 + 3) * 128 + n] = rb[r].w;
        }
        __syncthreads();
        if (kc < 3) LOAD_CHUNK(kc + 1);
#pragma unroll 8
        for (int k = 0; k < 32; k++) {
            unsigned long long a2[4];
#pragma unroll
            for (int mm = 0; mm < 4; mm++) {
                float av = As[(ty * 4 + mm) * 32 + k];
                a2[mm] = pack2(av, av);
            }
            const ulonglong2* bp = (const ulonglong2*)(Bs + k * 128 + tx * 8);
            ulonglong2 p0 = bp[0], p1 = bp[1];
            unsigned long long b2[4] = {p0.x, p0.y, p1.x, p1.y};
#pragma unroll
            for (int mm = 0; mm < 4; mm++)
#pragma unroll
                for (int c = 0; c < 4; c++)
                    ffma2(acc[mm][c], a2[mm], b2[c]);
        }
    }
#undef LOAD_CHUNK
#pragma unroll
    for (int mm = 0; mm < 4; mm++) {
        int m = m0 + ty * 4 + mm;
        float* orow = g_ih + (size_t)m * NG + n0 + tx * 8;
        float vals[8];
#pragma unroll
        for (int c = 0; c < 4; c++) {
            float lo, hi;
            unpack2(acc[mm][c], lo, hi);
            int n = n0 + tx * 8 + c * 2;
            vals[c * 2]     = lo + b_ih[n];
            vals[c * 2 + 1] = hi + b_ih[n + 1];
        }
        ((float4*)orow)[0] = make_float4(vals[0], vals[1], vals[2], vals[3]);
        ((float4*)orow)[1] = make_float4(vals[4], vals[5], vals[6], vals[7]);
    }
}

// ---------------- Mega kernel: scan producers (CTA 0..31) + jac consumers ----------------
__global__ void __launch_bounds__(384, 1) mega_kernel(
    const float* __restrict__ W_hh, const float* __restrict__ b_hh,
    const float* __restrict__ W_y,  const float* __restrict__ b_y,
    float* __restrict__ out)
{
    const int tid = threadIdx.x;

    if (blockIdx.x < NB) {
        // ================= PRODUCER: GRU scan for batch b =================
        const int b = blockIdx.x;
        const int g = tid;
        const int role = g >> 7;        // 0: r-rows, 1: z-rows, 2: n-rows
        const int j = g & 127;

        __shared__ __align__(16) float h_sh[NH];
        __shared__ __align__(8) float2 rp_sh[NH];   // (r, r*(1-r))
        __shared__ __align__(8) float2 zp_sh[NH];   // (z, z*(1-z))

        unsigned long long w2[64];
        const unsigned long long* wrow =
            (const unsigned long long*)(W_hh + (size_t)g * NH);
#pragma unroll
        for (int k2 = 0; k2 < 64; k2++) w2[k2] = wrow[k2];
        const float bh = b_hh[g];

        if (g < NH) h_sh[g] = 0.0f;

        const float* ihp = g_ih + (size_t)b * NS * NG;
        float ih_next = ihp[g];           // s = 0, own gate value (coalesced)
        __syncthreads();

        for (int s = 0; s < NS; s++) {
            float ih_cur = ih_next;
            if (s + 1 < NS) ih_next = ihp[(size_t)(s + 1) * NG + g];

            // hh[g] = W_hh[g,:] . h + b_hh[g]  (f32x2)
            unsigned long long acc[4] = {0ull, 0ull, 0ull, 0ull};
            const ulonglong2* h4 = (const ulonglong2*)h_sh;
#pragma unroll
            for (int k4 = 0; k4 < 32; k4++) {
                ulonglong2 hv = h4[k4];
                ffma2(acc[(2 * k4) & 3],     w2[2 * k4],     hv.x);
                ffma2(acc[(2 * k4 + 1) & 3], w2[2 * k4 + 1], hv.y);
            }
            float l0, h0, l1, h1, l2, h2, l3, h3;
            unpack2(acc[0], l0, h0); unpack2(acc[1], l1, h1);
            unpack2(acc[2], l2, h2); unpack2(acc[3], l3, h3);
            float sum = ((l0 + h0) + (l1 + h1)) + ((l2 + h2) + (l3 + h3)) + bh;

            const size_t cb = ((size_t)(s * NB + b)) * (4 * NH);
            // phase 1: parallel sigmoids, no hh smem round-trip
            if (role == 0) {
                float r = sigf(ih_cur + sum);
                rp_sh[j] = make_float2(r, r * (1.0f - r));
            } else if (role == 1) {
                float z = sigf(ih_cur + sum);
                zp_sh[j] = make_float2(z, z * (1.0f - z));
                g_coef[cb + 3 * NH + j] = z;
                if ((s & (FLAG_STEP - 1)) == FLAG_STEP - 1)
                    __threadfence();
            }
            __syncthreads();

            // phase 2: n-chain on threads 256..383 (M register-resident)
            if (role == 2) {
                float M = sum;
                float2 rp = rp_sh[j];
                float2 zp = zp_sh[j];
                float hp = h_sh[j];
                float n = tanh_fast(ih_cur + rp.x * M);
                float c67 = (1.0f - n * n) * (1.0f - zp.x);
                g_coef[cb + j]          = rp.y * M * c67;     // cr
                g_coef[cb + NH + j]     = rp.x * c67;         // cn
                g_coef[cb + 2 * NH + j] = zp.y * (hp - n);    // cz
                h_sh[j] = n + zp.x * (hp - n);                // h_new
                if ((s & (FLAG_STEP - 1)) == FLAG_STEP - 1)
                    __threadfence();
            }
            __syncthreads();
            if (g == 0 && (s & (FLAG_STEP - 1)) == FLAG_STEP - 1)
                red_add_release(&g_flag[s >> 3], 1u);
        }

        // y = h_last @ W_y^T + b_y
        if (g < NO) {
            float a = b_y[g];
            const float* wy = W_y + (size_t)g * NH;
#pragma unroll
            for (int k = 0; k < NH; k++) a = fmaf(wy[k], h_sh[k], a);
            out[b * NO + g] = a;
        }
    } else {
        // ================= CONSUMER: Jacobian materialization =================
        const int c0 = blockIdx.x - NB;     // 0..115
        const int w = tid >> 5;             // warp 0..11 -> i rows
        const int lane = tid & 31;
        const int j0 = lane * 4;
        float* jac = out + NB * NO;

        int scready = -1;
        for (int t = c0; t < NS * NB; t += NCONS) {
            int s = t >> 5;
            int b = t & 31;
            int sc = s >> 3;
            if (sc != scready) {
                if (tid == 0) {
                    while (ld_acquire(&g_flag[sc]) < (unsigned)NB) __nanosleep(128);
                }
                __syncthreads();
                scready = sc;
            }
            const float4* cp = (const float4*)(g_coef + (size_t)t * (4 * NH));
            float4 cr = cp[lane];
            float4 cn = cp[32 + lane];
            float4 cz = cp[64 + lane];
            float4 zz = cp[96 + lane];
            float* obase = jac + ((size_t)((NS - 1 - s) * NB + b)) * (NH * NH);
            for (int i = w; i < NH; i += 12) {
                const float4* wp = (const float4*)(g_wT + (size_t)i * NG);
                float4 wr = wp[lane];          // W_hh[j, i]
                float4 wz = wp[32 + lane];     // W_hh[H+j, i]
                float4 wn = wp[64 + lane];     // W_hh[2H+j, i]
                float4 v;
                v.x = fmaf(wr.x, cr.x, fmaf(wn.x, cn.x, wz.x * cz.x));
                v.y = fmaf(wr.y, cr.y, fmaf(wn.y, cn.y, wz.y * cz.y));
                v.z = fmaf(wr.z, cr.z, fmaf(wn.z, cn.z, wz.z * cz.z));
                v.w = fmaf(wr.w, cr.w, fmaf(wn.w, cn.w, wz.w * cz.w));
                if ((i >> 2) == lane) {        // diagonal: j == i
                    int d = i & 3;
                    if (d == 0) v.x += zz.x;
                    else if (d == 1) v.y += zz.y;
                    else if (d == 2) v.z += zz.z;
                    else v.w += zz.w;
                }
                *(float4*)(obase + i * NH + j0) = v;
            }
        }
    }
}

// ---------------- launch ----------------
extern "C" void kernel_launch(void* const* d_in, const int* in_sizes, int n_in,
                              void* d_out, int out_size) {
    const float* x    = (const float*)d_in[0];
    const float* W_ih = (const float*)d_in[1];
    const float* W_hh = (const float*)d_in[2];
    const float* b_ih = (const float*)d_in[3];
    const float* b_hh = (const float*)d_in[4];
    const float* W_y  = (const float*)d_in[5];
    const float* b_y  = (const float*)d_in[6];
    float* out = (float*)d_out;

    ih_gemm_kernel<<<dim3(256, 3), 256>>>(x, W_ih, b_ih, W_hh);
    mega_kernel<<<NB + NCONS, NG>>>(W_hh, b_hh, W_y, b_y, out);
}